// round 15
// baseline (speedup 1.0000x reference)
#include <cuda_runtime.h>
#include <cuda_fp16.h>
#include <cstdint>

#define BSZ 2
#define SEQ 2048
#define CH  1024
#define NH  16
#define DH  64
#define NOUT 1024

// fp16 copies of inputs (g_hxk doubles as the V source) + projected Q/K.
__device__ __half g_hxq[BSZ * SEQ * CH];
__device__ __half g_hxk[BSZ * SEQ * CH];
__device__ __half g_hwq[CH * NOUT];
__device__ __half g_hwk[CH * NOUT];
__device__ __half g_q[BSZ * NH * SEQ * DH];
__device__ __half g_k[BSZ * NH * SEQ * DH];   // K stored COMPACTED per batch

// Compacted unmasked-key index list per batch (padded to 128) and counts.
__device__ int g_idx[BSZ][SEQ + 128];
__device__ int g_cnt[BSZ];

#define LOG2E 1.4426950408889634f

// ---------------------------------------------------------------------------
// Helpers
// ---------------------------------------------------------------------------
__device__ __forceinline__ uint32_t f2h2(float lo, float hi) {
    __half2 h = __floats2half2_rn(lo, hi);
    return *reinterpret_cast<uint32_t*>(&h);
}
__device__ __forceinline__ uint32_t sptr(const void* p) {
    return (uint32_t)__cvta_generic_to_shared(p);
}
__device__ __forceinline__ uint32_t hex2(uint32_t x) {   // exp2 on packed f16x2
    uint32_t r;
    asm("ex2.approx.f16x2 %0, %1;" : "=r"(r) : "r"(x));
    return r;
}

__device__ __forceinline__ void mma_f16(float* d, const uint32_t* a,
                                        uint32_t b0, uint32_t b1, const float* c) {
    asm volatile(
        "mma.sync.aligned.m16n8k16.row.col.f32.f16.f16.f32 "
        "{%0,%1,%2,%3}, {%4,%5,%6,%7}, {%8,%9}, {%10,%11,%12,%13};"
        : "=f"(d[0]), "=f"(d[1]), "=f"(d[2]), "=f"(d[3])
        : "r"(a[0]), "r"(a[1]), "r"(a[2]), "r"(a[3]),
          "r"(b0), "r"(b1),
          "f"(c[0]), "f"(c[1]), "f"(c[2]), "f"(c[3]));
}

#define LDSM4(r0, r1, r2, r3, a) \
    asm volatile("ldmatrix.sync.aligned.m8n8.x4.shared.b16 {%0,%1,%2,%3}, [%4];" \
        : "=r"(r0), "=r"(r1), "=r"(r2), "=r"(r3) : "r"(a))
#define LDSM4T(r0, r1, r2, r3, a) \
    asm volatile("ldmatrix.sync.aligned.m8n8.x4.trans.shared.b16 {%0,%1,%2,%3}, [%4];" \
        : "=r"(r0), "=r"(r1), "=r"(r2), "=r"(r3) : "r"(a))

#define CP16(dst, src) \
    asm volatile("cp.async.cg.shared.global [%0], [%1], 16;" \
        :: "r"(dst), "l"(src) : "memory")
#define CP_COMMIT  asm volatile("cp.async.commit_group;" ::: "memory")
#define CP_WAIT1   asm volatile("cp.async.wait_group 1;" ::: "memory")
#define CP_WAIT0   asm volatile("cp.async.wait_group 0;" ::: "memory")

// ---------------------------------------------------------------------------
// Fused pre-pass: blocks 0..BSZ-1 compact the mask (pad idx to 128-aligned);
// the rest convert fp32->fp16. NEW: loads go cp.async -> smem (register-free
// MLP, 2048 in-flight transfers per block) then each thread converts its own
// staged bytes. Masked keys contribute EXACTLY 0 in the fp32 reference, so
// dropping them is exact.
// ---------------------------------------------------------------------------
#define NX4 ((BSZ * SEQ * CH) / 4)   // 1048576
#define NW4 ((CH * NOUT) / 4)        // 262144
#define CVT_TOTAL (2 * NX4 + 2 * NW4)
#define CVT_BLOCKS (CVT_TOTAL / 2048)

__global__ __launch_bounds__(256) void pre_kernel(
    const int*    __restrict__ mask,
    const float4* __restrict__ xq, const float4* __restrict__ xk,
    const float4* __restrict__ wq, const float4* __restrict__ wk)
{
    __shared__ __align__(16) float4 stg[2048];   // 32 KB stage
    const int t = threadIdx.x;
    if (blockIdx.x < BSZ) {
        const int b = blockIdx.x;
        __shared__ int scnt;
        if (t == 0) scnt = 0;
        __syncthreads();
        #pragma unroll
        for (int u = 0; u < SEQ / 256; u++) {
            const int j = u * 256 + t;
            const int m = mask[b * SEQ + j];
            const unsigned bal = __ballot_sync(0xffffffffu, m != 0);
            int base = 0;
            if ((t & 31) == 0) base = atomicAdd(&scnt, __popc(bal));
            base = __shfl_sync(0xffffffffu, base, 0);
            if (m) g_idx[b][base + __popc(bal & ((1u << (t & 31)) - 1u))] = j;
        }
        __syncthreads();
        const int total   = scnt;
        const int padded  = (total + 127) & ~127;
        for (int p = total + t; p < padded; p += 256) g_idx[b][p] = 0;
        if (t == 0) g_cnt[b] = total;
        return;
    }
    const int blk = blockIdx.x - BSZ;
    uint2* dp[8];
    #pragma unroll
    for (int u = 0; u < 8; u++) {
        const int i = blk * 2048 + u * 256 + t;
        const float4* src;
        uint2* dst;
        int j;
        if (i < NX4)                { src = xq; dst = (uint2*)g_hxq; j = i; }
        else if (i < 2 * NX4)       { src = xk; dst = (uint2*)g_hxk; j = i - NX4; }
        else if (i < 2 * NX4 + NW4) { src = wq; dst = (uint2*)g_hwq; j = i - 2 * NX4; }
        else                        { src = wk; dst = (uint2*)g_hwk; j = i - 2 * NX4 - NW4; }
        CP16(sptr(&stg[u * 256 + t]), src + j);
        dp[u] = dst + j;
    }
    CP_COMMIT;
    CP_WAIT0;
    __syncwarp();
    #pragma unroll
    for (int u = 0; u < 8; u++) {
        const float4 v = stg[u * 256 + t];
        *dp[u] = make_uint2(f2h2(v.x, v.y), f2h2(v.z, v.w));
    }
}

// ---------------------------------------------------------------------------
// Projection GEMM, fp16 in/out, cp.async triple-buffered, K-step 64. (unchanged)
// ---------------------------------------------------------------------------
#define PXSTR 72
#define PWSTR 136
#define XSTG (128 * PXSTR * 2)
#define WSTG (64 * PWSTR * 2)
#define PROJ_NKT (CH / 64)

__global__ __launch_bounds__(256, 2) void proj_mma_kernel(
    const float* __restrict__ bq, const float* __restrict__ bk)
{
    __shared__ __align__(16) __half Xs[3][128][PXSTR];
    __shared__ __align__(16) __half Ws[3][64][PWSTR];

    const int t   = threadIdx.x;
    const int lid = t & 31;
    const int wid = t >> 5;
    const int warpm = wid & 3;
    const int warpn = wid >> 2;
    const int g  = lid >> 2;
    const int tg = lid & 3;
    const int lg = lid >> 3;
    const int lr = lid & 7;

    const bool is_k = (blockIdx.z != 0);
    const __half* W    = is_k ? g_hwk : g_hwq;
    const float*  bias = is_k ? bk    : bq;
    __half*       out  = is_k ? g_k   : g_q;
    const float scale  = is_k ? 1.0f : 0.125f * LOG2E;

    const int n0 = blockIdx.y * 128;

    int xrow[4], xseg[4], wrow[4], wseg[4];
    #pragma unroll
    for (int i = 0; i < 4; i++) {
        const int xi = t + i * 256;
        xrow[i] = xi >> 3;  xseg[i] = (xi & 7) * 8;
        wrow[i] = xi >> 4;  wseg[i] = (xi & 15) * 8;
    }

    int kb = 0, m0l = 0;
    int m0 = blockIdx.x * 128;
    const __half* xptr[4];
    if (!is_k) {
        #pragma unroll
        for (int i = 0; i < 4; i++)
            xptr[i] = g_hxq + (size_t)(m0 + xrow[i]) * CH;
    } else {
        kb  = blockIdx.x >> 4;
        m0l = (blockIdx.x & 15) * 128;
        const int padded = (g_cnt[kb] + 127) & ~127;
        if (m0l >= padded) return;
        #pragma unroll
        for (int i = 0; i < 4; i++)
            xptr[i] = g_hxk + ((size_t)kb * SEQ + g_idx[kb][m0l + xrow[i]]) * CH;
    }

    #define PROJ_ISSUE(buf, k0) do {                                           \
        _Pragma("unroll")                                                      \
        for (int i = 0; i < 4; i++) {                                          \
            CP16(sptr(&Xs[buf][xrow[i]][xseg[i]]), xptr[i] + (k0) + xseg[i]);  \
            CP16(sptr(&Ws[buf][wrow[i]][wseg[i]]),                             \
                 W + (size_t)((k0) + wrow[i]) * NOUT + n0 + wseg[i]);          \
        } CP_COMMIT; } while (0)

    uint32_t aaddr[2], baddr[4];
    #pragma unroll
    for (int mf = 0; mf < 2; mf++)
        aaddr[mf] = sptr(&Xs[0][warpm * 32 + mf * 16 + (lg & 1) * 8 + lr][(lg >> 1) * 8]);
    #pragma unroll
    for (int np = 0; np < 4; np++)
        baddr[np] = sptr(&Ws[0][(lg & 1) * 8 + lr][warpn * 64 + np * 16 + (lg >> 1) * 8]);

    float acc[2][8][4] = {};

    PROJ_ISSUE(0, 0);
    PROJ_ISSUE(1, 64);

    int cur = 0, nxt2 = 2;
    for (int kt = 0; kt < PROJ_NKT; kt++) {
        if (kt + 1 < PROJ_NKT) { CP_WAIT1; } else { CP_WAIT0; }
        __syncthreads();
        if (kt + 2 < PROJ_NKT)
            PROJ_ISSUE(nxt2, (kt + 2) * 64);

        const uint32_t xo = cur * XSTG;
        const uint32_t wo = cur * WSTG;
        #pragma unroll
        for (int ks = 0; ks < 4; ks++) {
            uint32_t af[2][4], bf[4][4];
            #pragma unroll
            for (int mf = 0; mf < 2; mf++)
                LDSM4(af[mf][0], af[mf][1], af[mf][2], af[mf][3],
                      aaddr[mf] + xo + ks * 32);
            #pragma unroll
            for (int np = 0; np < 4; np++)
                LDSM4T(bf[np][0], bf[np][1], bf[np][2], bf[np][3],
                       baddr[np] + wo + ks * 16 * (PWSTR * 2));
            #pragma unroll
            for (int mf = 0; mf < 2; mf++)
                #pragma unroll
                for (int nf = 0; nf < 8; nf++)
                    mma_f16(acc[mf][nf], af[mf],
                            bf[nf >> 1][(nf & 1) * 2],
                            bf[nf >> 1][(nf & 1) * 2 + 1],
                            acc[mf][nf]);
        }

        cur  = (cur  == 2) ? 0 : cur + 1;
        nxt2 = (nxt2 == 2) ? 0 : nxt2 + 1;
    }

    #pragma unroll
    for (int mf = 0; mf < 2; mf++) {
        const int rloc = warpm * 32 + mf * 16 + g;
        const int b = is_k ? kb : ((m0 + rloc) >> 11);
        const int s = is_k ? (m0l + rloc) : ((m0 + rloc) & 2047);
        #pragma unroll
        for (int nf = 0; nf < 8; nf++) {
            const int gn = n0 + warpn * 64 + nf * 8 + tg * 2;
            const int h = gn >> 6, d = gn & 63;
            const float b0v = bias[gn], b1v = bias[gn + 1];
            uint32_t v0 = f2h2((acc[mf][nf][0] + b0v) * scale,
                               (acc[mf][nf][1] + b1v) * scale);
            uint32_t v1 = f2h2((acc[mf][nf][2] + b0v) * scale,
                               (acc[mf][nf][3] + b1v) * scale);
            *(uint32_t*)(out + ((size_t)(b * NH + h) * SEQ + s) * DH + d)       = v0;
            *(uint32_t*)(out + ((size_t)(b * NH + h) * SEQ + (s + 8)) * DH + d) = v1;
        }
    }
}

// ---------------------------------------------------------------------------
// Flash attention over COMPACTED keys. 32 q-rows per warp (2 m-frags),
// 128 q-rows per CTA, triple-buffered rings. (unchanged)
// ---------------------------------------------------------------------------
#define KST 72
#define KSTAGE_B (64 * KST * 2)
#define ATTN_SMEM (6 * KSTAGE_B)

__global__ __launch_bounds__(128, 2) void attn_mma_kernel(
    float* __restrict__ out)    // [B, S, H, D] fp32
{
    extern __shared__ __align__(16) char dsm[];
    __half* Ksm = (__half*)dsm;                       // [3][64][KST]
    __half* Vsm = (__half*)(dsm + 3 * KSTAGE_B);      // [3][64][KST]

    const int t   = threadIdx.x;
    const int lid = t & 31;
    const int wid = t >> 5;
    const int g   = lid >> 2;
    const int tg  = lid & 3;
    const int lg  = lid >> 3;
    const int lr  = lid & 7;
    const int q0  = blockIdx.x * 128;
    const int bh  = blockIdx.y;
    const int b   = bh >> 4;
    const int h   = bh & 15;

    const __half* qbase = g_q + ((size_t)bh * SEQ + q0) * DH;
    const __half* kbase = g_k + (size_t)bh * SEQ * DH;     // compacted rows
    const __half* vbase = g_hxk + (size_t)b * SEQ * CH + h * DH;
    const int*    idx   = g_idx[b];

    const int cnt = g_cnt[b];
    const int nkt = (cnt + 63) >> 6;

    const int krow[4] = { (t + 0) >> 3, (t + 128) >> 3, (t + 256) >> 3, (t + 384) >> 3 };
    const int kseg[4] = { ((t + 0) & 7) * 8, ((t + 128) & 7) * 8,
                          ((t + 256) & 7) * 8, ((t + 384) & 7) * 8 };

    #define ATTN_ISSUE(buf, k0) do {                                           \
        int _r[4];                                                             \
        _Pragma("unroll")                                                      \
        for (int i = 0; i < 4; i++) _r[i] = idx[(k0) + krow[i]];               \
        _Pragma("unroll")                                                      \
        for (int i = 0; i < 4; i++) {                                          \
            CP16(sptr(&Ksm[(buf) * (64 * KST) + krow[i] * KST + kseg[i]]),     \
                 kbase + (size_t)((k0) + krow[i]) * DH + kseg[i]);             \
            CP16(sptr(&Vsm[(buf) * (64 * KST) + krow[i] * KST + kseg[i]]),     \
                 vbase + (size_t)_r[i] * CH + kseg[i]);                        \
        } CP_COMMIT; } while (0)

    // Stage Q (128x64) into stage-2 buffers: rows 0-63 -> Ksm[2], 64-127 -> Vsm[2]
    #pragma unroll
    for (int i = 0; i < 8; i++) {
        const int iidx = t + i * 128;
        const int row = iidx >> 3, u4 = (iidx & 7) * 8;
        uint4 v = *(const uint4*)(qbase + (size_t)row * DH + u4);
        __half* dst = (row < 64) ? &Ksm[2 * (64 * KST) + row * KST + u4]
                                 : &Vsm[2 * (64 * KST) + (row - 64) * KST + u4];
        *(uint4*)dst = v;
    }
    __syncthreads();

    uint32_t qf[2][4][4];
    #pragma unroll
    for (int mf = 0; mf < 2; mf++) {
        const int r = wid * 32 + mf * 16 + (lg & 1) * 8 + lr;
        const __half* qp = (r < 64) ? &Ksm[2 * (64 * KST) + r * KST + (lg >> 1) * 8]
                                    : &Vsm[2 * (64 * KST) + (r - 64) * KST + (lg >> 1) * 8];
        const uint32_t qa = sptr(qp);
        #pragma unroll
        for (int ks = 0; ks < 4; ks++)
            LDSM4(qf[mf][ks][0], qf[mf][ks][1], qf[mf][ks][2], qf[mf][ks][3],
                  qa + ks * 32);
    }

    ATTN_ISSUE(0, 0);
    if (nkt > 1) ATTN_ISSUE(1, 64);

    const uint32_t kbase_a = sptr(&Ksm[((lg >> 1) * 8 + lr) * KST + (lg & 1) * 8]);
    const uint32_t vbase_a = sptr(&Vsm[((lg & 1) * 8 + lr) * KST + (lg >> 1) * 8]);

    const uint32_t bones = (g == 0) ? 0x3C003C00u : 0u;

    float o[2][8][4] = {};
    float ol[2][4] = {};

    int cur = 0, nxt2 = 2;
    for (int kt = 0; kt < nkt; kt++) {
        const int k0 = kt * 64;
        if (kt + 1 < nkt) { CP_WAIT1; } else { CP_WAIT0; }
        __syncthreads();
        if (kt + 2 < nkt)
            ATTN_ISSUE(nxt2, k0 + 128);

        const uint32_t ko = kbase_a + cur * KSTAGE_B;
        const uint32_t vo = vbase_a + cur * KSTAGE_B;

        // S = Q K^T for both m-frags; pad-column kill only on the last tile.
        float s[2][8][4];
        if (k0 + 64 <= cnt) {
            #pragma unroll
            for (int mf = 0; mf < 2; mf++)
                #pragma unroll
                for (int nf = 0; nf < 8; nf++)
                    s[mf][nf][0] = s[mf][nf][1] = s[mf][nf][2] = s[mf][nf][3] = 0.0f;
        } else {
            #pragma unroll
            for (int nf = 0; nf < 8; nf++) {
                const int c0 = k0 + nf * 8 + tg * 2;
                const float ma = (c0     < cnt) ? 0.0f : -1000.0f;
                const float mb = (c0 + 1 < cnt) ? 0.0f : -1000.0f;
                #pragma unroll
                for (int mf = 0; mf < 2; mf++) {
                    s[mf][nf][0] = ma; s[mf][nf][1] = mb;
                    s[mf][nf][2] = ma; s[mf][nf][3] = mb;
                }
            }
        }
        #pragma unroll
        for (int ks = 0; ks < 4; ks++) {
            uint32_t bfv[4][4];
            #pragma unroll
            for (int p = 0; p < 4; p++)
                LDSM4(bfv[p][0], bfv[p][1], bfv[p][2], bfv[p][3],
                      ko + p * 16 * (KST * 2) + ks * 32);
            #pragma unroll
            for (int nf = 0; nf < 8; nf++) {
                const uint32_t b0 = bfv[nf >> 1][(nf & 1) * 2];
                const uint32_t b1 = bfv[nf >> 1][(nf & 1) * 2 + 1];
                mma_f16(s[0][nf], qf[0][ks], b0, b1, s[0][nf]);
                mma_f16(s[1][nf], qf[1][ks], b0, b1, s[1][nf]);
            }
        }

        // P = exp2(S) on packed f16x2
        uint32_t ph[2][8][2];
        #pragma unroll
        for (int mf = 0; mf < 2; mf++)
            #pragma unroll
            for (int nf = 0; nf < 8; nf++) {
                ph[mf][nf][0] = hex2(f2h2(s[mf][nf][0], s[mf][nf][1]));
                ph[mf][nf][1] = hex2(f2h2(s[mf][nf][2], s[mf][nf][3]));
            }

        // O += P V ; l += P 1 (ones-column MMA), both m-frags share V frags.
        #pragma unroll
        for (int j = 0; j < 4; j++) {
            uint32_t a0[4] = { ph[0][2 * j][0], ph[0][2 * j][1],
                               ph[0][2 * j + 1][0], ph[0][2 * j + 1][1] };
            uint32_t a1[4] = { ph[1][2 * j][0], ph[1][2 * j][1],
                               ph[1][2 * j + 1][0], ph[1][2 * j + 1][1] };
            mma_f16(ol[0], a0, bones, bones, ol[0]);
            mma_f16(ol[1], a1, bones, bones, ol[1]);
            #pragma unroll
            for (int p = 0; p < 4; p++) {
                uint32_t vf[4];
                LDSM4T(vf[0], vf[1], vf[2], vf[3],
                       vo + j * 16 * (KST * 2) + p * 32);
                mma_f16(o[0][2 * p],     a0, vf[0], vf[1], o[0][2 * p]);
                mma_f16(o[0][2 * p + 1], a0, vf[2], vf[3], o[0][2 * p + 1]);
                mma_f16(o[1][2 * p],     a1, vf[0], vf[1], o[1][2 * p]);
                mma_f16(o[1][2 * p + 1], a1, vf[2], vf[3], o[1][2 * p + 1]);
            }
        }

        cur  = (cur  == 2) ? 0 : cur + 1;
        nxt2 = (nxt2 == 2) ? 0 : nxt2 + 1;
    }

    #pragma unroll
    for (int mf = 0; mf < 2; mf++) {
        const float l0 = __shfl_sync(0xffffffffu, ol[mf][0], lid & ~3);
        const float l1 = __shfl_sync(0xffffffffu, ol[mf][2], lid & ~3);
        const float inv0 = 1.0f / l0;
        const float inv1 = 1.0f / l1;
        const int r0 = q0 + wid * 32 + mf * 16 + g;
        #pragma unroll
        for (int nf = 0; nf < 8; nf++) {
            const int d = nf * 8 + tg * 2;
            float2 v0 = make_float2(o[mf][nf][0] * inv0, o[mf][nf][1] * inv0);
            float2 v1 = make_float2(o[mf][nf][2] * inv1, o[mf][nf][3] * inv1);
            *(float2*)(out + (((size_t)b * SEQ + r0) * NH + h) * DH + d)     = v0;
            *(float2*)(out + (((size_t)b * SEQ + r0 + 8) * NH + h) * DH + d) = v1;
        }
    }
}

// ---------------------------------------------------------------------------
extern "C" void kernel_launch(void* const* d_in, const int* in_sizes, int n_in,
                              void* d_out, int out_size)
{
    const float* q_in  = (const float*)d_in[0];
    const float* k_in  = (const float*)d_in[1];
    const int*   mask  = (const int*)d_in[2];
    const float* Wq    = (const float*)d_in[3];
    const float* bq    = (const float*)d_in[4];
    const float* Wk    = (const float*)d_in[5];
    const float* bk    = (const float*)d_in[6];
    float*       out   = (float*)d_out;

    pre_kernel<<<CVT_BLOCKS + BSZ, 256>>>(mask,
                                          (const float4*)q_in, (const float4*)k_in,
                                          (const float4*)Wq, (const float4*)Wk);

    dim3 pgrid((BSZ * SEQ) / 128, NOUT / 128, 2);
    proj_mma_kernel<<<pgrid, 256>>>(bq, bk);

    cudaFuncSetAttribute(attn_mma_kernel,
                         cudaFuncAttributeMaxDynamicSharedMemorySize, ATTN_SMEM);
    dim3 agrid(SEQ / 128, BSZ * NH);
    attn_mma_kernel<<<agrid, 128, ATTN_SMEM>>>(out);
}

// round 16
// speedup vs baseline: 1.0184x; 1.0184x over previous
#include <cuda_runtime.h>
#include <cuda_fp16.h>
#include <cstdint>

#define BSZ 2
#define SEQ 2048
#define CH  1024
#define NH  16
#define DH  64
#define NOUT 1024

// fp16 copies of inputs (g_hxk doubles as the V source) + projected Q/K.
__device__ __half g_hxq[BSZ * SEQ * CH];
__device__ __half g_hxk[BSZ * SEQ * CH];
__device__ __half g_hwq[CH * NOUT];
__device__ __half g_hwk[CH * NOUT];
__device__ __half g_q[BSZ * NH * SEQ * DH];
__device__ __half g_k[BSZ * NH * SEQ * DH];   // K stored COMPACTED per batch

// Compacted unmasked-key index list per batch (padded to 128) and counts.
__device__ int g_idx[BSZ][SEQ + 128];
__device__ int g_cnt[BSZ];

#define LOG2E 1.4426950408889634f

// ---------------------------------------------------------------------------
// Helpers
// ---------------------------------------------------------------------------
__device__ __forceinline__ uint32_t f2h2(float lo, float hi) {
    __half2 h = __floats2half2_rn(lo, hi);
    return *reinterpret_cast<uint32_t*>(&h);
}
__device__ __forceinline__ uint32_t sptr(const void* p) {
    return (uint32_t)__cvta_generic_to_shared(p);
}
__device__ __forceinline__ uint32_t hex2(uint32_t x) {   // exp2 on packed f16x2
    uint32_t r;
    asm("ex2.approx.f16x2 %0, %1;" : "=r"(r) : "r"(x));
    return r;
}

__device__ __forceinline__ void mma_f16(float* d, const uint32_t* a,
                                        uint32_t b0, uint32_t b1, const float* c) {
    asm volatile(
        "mma.sync.aligned.m16n8k16.row.col.f32.f16.f16.f32 "
        "{%0,%1,%2,%3}, {%4,%5,%6,%7}, {%8,%9}, {%10,%11,%12,%13};"
        : "=f"(d[0]), "=f"(d[1]), "=f"(d[2]), "=f"(d[3])
        : "r"(a[0]), "r"(a[1]), "r"(a[2]), "r"(a[3]),
          "r"(b0), "r"(b1),
          "f"(c[0]), "f"(c[1]), "f"(c[2]), "f"(c[3]));
}

#define LDSM4(r0, r1, r2, r3, a) \
    asm volatile("ldmatrix.sync.aligned.m8n8.x4.shared.b16 {%0,%1,%2,%3}, [%4];" \
        : "=r"(r0), "=r"(r1), "=r"(r2), "=r"(r3) : "r"(a))
#define LDSM4T(r0, r1, r2, r3, a) \
    asm volatile("ldmatrix.sync.aligned.m8n8.x4.trans.shared.b16 {%0,%1,%2,%3}, [%4];" \
        : "=r"(r0), "=r"(r1), "=r"(r2), "=r"(r3) : "r"(a))

#define CP16(dst, src) \
    asm volatile("cp.async.cg.shared.global [%0], [%1], 16;" \
        :: "r"(dst), "l"(src) : "memory")
#define CP_COMMIT  asm volatile("cp.async.commit_group;" ::: "memory")
#define CP_WAIT1   asm volatile("cp.async.wait_group 1;" ::: "memory")
#define CP_WAIT0   asm volatile("cp.async.wait_group 0;" ::: "memory")

// ---------------------------------------------------------------------------
// Fused pre-pass: blocks 0..BSZ-1 compact the mask (pad idx to 128-aligned);
// the rest convert fp32->fp16 (cp.async-staged). At ~3.4 TB/s mixed R/W this
// is HBM-floor-bound. Triggers successor launch at entry (PDL).
// ---------------------------------------------------------------------------
#define NX4 ((BSZ * SEQ * CH) / 4)   // 1048576
#define NW4 ((CH * NOUT) / 4)        // 262144
#define CVT_TOTAL (2 * NX4 + 2 * NW4)
#define CVT_BLOCKS (CVT_TOTAL / 2048)

__global__ __launch_bounds__(256) void pre_kernel(
    const int*    __restrict__ mask,
    const float4* __restrict__ xq, const float4* __restrict__ xk,
    const float4* __restrict__ wq, const float4* __restrict__ wk)
{
    cudaTriggerProgrammaticLaunchCompletion();   // let proj launch into our tail
    __shared__ __align__(16) float4 stg[2048];   // 32 KB stage
    const int t = threadIdx.x;
    if (blockIdx.x < BSZ) {
        const int b = blockIdx.x;
        __shared__ int scnt;
        if (t == 0) scnt = 0;
        __syncthreads();
        #pragma unroll
        for (int u = 0; u < SEQ / 256; u++) {
            const int j = u * 256 + t;
            const int m = mask[b * SEQ + j];
            const unsigned bal = __ballot_sync(0xffffffffu, m != 0);
            int base = 0;
            if ((t & 31) == 0) base = atomicAdd(&scnt, __popc(bal));
            base = __shfl_sync(0xffffffffu, base, 0);
            if (m) g_idx[b][base + __popc(bal & ((1u << (t & 31)) - 1u))] = j;
        }
        __syncthreads();
        const int total   = scnt;
        const int padded  = (total + 127) & ~127;
        for (int p = total + t; p < padded; p += 256) g_idx[b][p] = 0;
        if (t == 0) g_cnt[b] = total;
        return;
    }
    const int blk = blockIdx.x - BSZ;
    uint2* dp[8];
    #pragma unroll
    for (int u = 0; u < 8; u++) {
        const int i = blk * 2048 + u * 256 + t;
        const float4* src;
        uint2* dst;
        int j;
        if (i < NX4)                { src = xq; dst = (uint2*)g_hxq; j = i; }
        else if (i < 2 * NX4)       { src = xk; dst = (uint2*)g_hxk; j = i - NX4; }
        else if (i < 2 * NX4 + NW4) { src = wq; dst = (uint2*)g_hwq; j = i - 2 * NX4; }
        else                        { src = wk; dst = (uint2*)g_hwk; j = i - 2 * NX4 - NW4; }
        CP16(sptr(&stg[u * 256 + t]), src + j);
        dp[u] = dst + j;
    }
    CP_COMMIT;
    CP_WAIT0;
    __syncwarp();
    #pragma unroll
    for (int u = 0; u < 8; u++) {
        const float4 v = stg[u * 256 + t];
        *dp[u] = make_uint2(f2h2(v.x, v.y), f2h2(v.z, v.w));
    }
}

// ---------------------------------------------------------------------------
// Projection GEMM, fp16 in/out, cp.async triple-buffered, K-step 64.
// PDL: waits on pre at entry, triggers attn's launch.
// ---------------------------------------------------------------------------
#define PXSTR 72
#define PWSTR 136
#define XSTG (128 * PXSTR * 2)
#define WSTG (64 * PWSTR * 2)
#define PROJ_NKT (CH / 64)

__global__ __launch_bounds__(256, 2) void proj_mma_kernel(
    const float* __restrict__ bq, const float* __restrict__ bk)
{
    cudaGridDependencySynchronize();             // pre outputs must be complete
    cudaTriggerProgrammaticLaunchCompletion();   // let attn launch into our tail

    __shared__ __align__(16) __half Xs[3][128][PXSTR];
    __shared__ __align__(16) __half Ws[3][64][PWSTR];

    const int t   = threadIdx.x;
    const int lid = t & 31;
    const int wid = t >> 5;
    const int warpm = wid & 3;
    const int warpn = wid >> 2;
    const int g  = lid >> 2;
    const int tg = lid & 3;
    const int lg = lid >> 3;
    const int lr = lid & 7;

    const bool is_k = (blockIdx.z != 0);
    const __half* W    = is_k ? g_hwk : g_hwq;
    const float*  bias = is_k ? bk    : bq;
    __half*       out  = is_k ? g_k   : g_q;
    const float scale  = is_k ? 1.0f : 0.125f * LOG2E;

    const int n0 = blockIdx.y * 128;

    int xrow[4], xseg[4], wrow[4], wseg[4];
    #pragma unroll
    for (int i = 0; i < 4; i++) {
        const int xi = t + i * 256;
        xrow[i] = xi >> 3;  xseg[i] = (xi & 7) * 8;
        wrow[i] = xi >> 4;  wseg[i] = (xi & 15) * 8;
    }

    int kb = 0, m0l = 0;
    int m0 = blockIdx.x * 128;
    const __half* xptr[4];
    if (!is_k) {
        #pragma unroll
        for (int i = 0; i < 4; i++)
            xptr[i] = g_hxq + (size_t)(m0 + xrow[i]) * CH;
    } else {
        kb  = blockIdx.x >> 4;
        m0l = (blockIdx.x & 15) * 128;
        const int padded = (g_cnt[kb] + 127) & ~127;
        if (m0l >= padded) return;
        #pragma unroll
        for (int i = 0; i < 4; i++)
            xptr[i] = g_hxk + ((size_t)kb * SEQ + g_idx[kb][m0l + xrow[i]]) * CH;
    }

    #define PROJ_ISSUE(buf, k0) do {                                           \
        _Pragma("unroll")                                                      \
        for (int i = 0; i < 4; i++) {                                          \
            CP16(sptr(&Xs[buf][xrow[i]][xseg[i]]), xptr[i] + (k0) + xseg[i]);  \
            CP16(sptr(&Ws[buf][wrow[i]][wseg[i]]),                             \
                 W + (size_t)((k0) + wrow[i]) * NOUT + n0 + wseg[i]);          \
        } CP_COMMIT; } while (0)

    uint32_t aaddr[2], baddr[4];
    #pragma unroll
    for (int mf = 0; mf < 2; mf++)
        aaddr[mf] = sptr(&Xs[0][warpm * 32 + mf * 16 + (lg & 1) * 8 + lr][(lg >> 1) * 8]);
    #pragma unroll
    for (int np = 0; np < 4; np++)
        baddr[np] = sptr(&Ws[0][(lg & 1) * 8 + lr][warpn * 64 + np * 16 + (lg >> 1) * 8]);

    float acc[2][8][4] = {};

    PROJ_ISSUE(0, 0);
    PROJ_ISSUE(1, 64);

    int cur = 0, nxt2 = 2;
    for (int kt = 0; kt < PROJ_NKT; kt++) {
        if (kt + 1 < PROJ_NKT) { CP_WAIT1; } else { CP_WAIT0; }
        __syncthreads();
        if (kt + 2 < PROJ_NKT)
            PROJ_ISSUE(nxt2, (kt + 2) * 64);

        const uint32_t xo = cur * XSTG;
        const uint32_t wo = cur * WSTG;
        #pragma unroll
        for (int ks = 0; ks < 4; ks++) {
            uint32_t af[2][4], bf[4][4];
            #pragma unroll
            for (int mf = 0; mf < 2; mf++)
                LDSM4(af[mf][0], af[mf][1], af[mf][2], af[mf][3],
                      aaddr[mf] + xo + ks * 32);
            #pragma unroll
            for (int np = 0; np < 4; np++)
                LDSM4T(bf[np][0], bf[np][1], bf[np][2], bf[np][3],
                       baddr[np] + wo + ks * 16 * (PWSTR * 2));
            #pragma unroll
            for (int mf = 0; mf < 2; mf++)
                #pragma unroll
                for (int nf = 0; nf < 8; nf++)
                    mma_f16(acc[mf][nf], af[mf],
                            bf[nf >> 1][(nf & 1) * 2],
                            bf[nf >> 1][(nf & 1) * 2 + 1],
                            acc[mf][nf]);
        }

        cur  = (cur  == 2) ? 0 : cur + 1;
        nxt2 = (nxt2 == 2) ? 0 : nxt2 + 1;
    }

    #pragma unroll
    for (int mf = 0; mf < 2; mf++) {
        const int rloc = warpm * 32 + mf * 16 + g;
        const int b = is_k ? kb : ((m0 + rloc) >> 11);
        const int s = is_k ? (m0l + rloc) : ((m0 + rloc) & 2047);
        #pragma unroll
        for (int nf = 0; nf < 8; nf++) {
            const int gn = n0 + warpn * 64 + nf * 8 + tg * 2;
            const int h = gn >> 6, d = gn & 63;
            const float b0v = bias[gn], b1v = bias[gn + 1];
            uint32_t v0 = f2h2((acc[mf][nf][0] + b0v) * scale,
                               (acc[mf][nf][1] + b1v) * scale);
            uint32_t v1 = f2h2((acc[mf][nf][2] + b0v) * scale,
                               (acc[mf][nf][3] + b1v) * scale);
            *(uint32_t*)(out + ((size_t)(b * NH + h) * SEQ + s) * DH + d)       = v0;
            *(uint32_t*)(out + ((size_t)(b * NH + h) * SEQ + (s + 8)) * DH + d) = v1;
        }
    }
}

// ---------------------------------------------------------------------------
// Flash attention over COMPACTED keys. 32 q-rows per warp (2 m-frags),
// 128 q-rows per CTA, triple-buffered rings. PDL: waits on proj at entry.
// ---------------------------------------------------------------------------
#define KST 72
#define KSTAGE_B (64 * KST * 2)
#define ATTN_SMEM (6 * KSTAGE_B)

__global__ __launch_bounds__(128, 2) void attn_mma_kernel(
    float* __restrict__ out)    // [B, S, H, D] fp32
{
    cudaGridDependencySynchronize();   // g_q / g_k must be complete

    extern __shared__ __align__(16) char dsm[];
    __half* Ksm = (__half*)dsm;                       // [3][64][KST]
    __half* Vsm = (__half*)(dsm + 3 * KSTAGE_B);      // [3][64][KST]

    const int t   = threadIdx.x;
    const int lid = t & 31;
    const int wid = t >> 5;
    const int g   = lid >> 2;
    const int tg  = lid & 3;
    const int lg  = lid >> 3;
    const int lr  = lid & 7;
    const int q0  = blockIdx.x * 128;
    const int bh  = blockIdx.y;
    const int b   = bh >> 4;
    const int h   = bh & 15;

    const __half* qbase = g_q + ((size_t)bh * SEQ + q0) * DH;
    const __half* kbase = g_k + (size_t)bh * SEQ * DH;     // compacted rows
    const __half* vbase = g_hxk + (size_t)b * SEQ * CH + h * DH;
    const int*    idx   = g_idx[b];

    const int cnt = g_cnt[b];
    const int nkt = (cnt + 63) >> 6;

    const int krow[4] = { (t + 0) >> 3, (t + 128) >> 3, (t + 256) >> 3, (t + 384) >> 3 };
    const int kseg[4] = { ((t + 0) & 7) * 8, ((t + 128) & 7) * 8,
                          ((t + 256) & 7) * 8, ((t + 384) & 7) * 8 };

    #define ATTN_ISSUE(buf, k0) do {                                           \
        int _r[4];                                                             \
        _Pragma("unroll")                                                      \
        for (int i = 0; i < 4; i++) _r[i] = idx[(k0) + krow[i]];               \
        _Pragma("unroll")                                                      \
        for (int i = 0; i < 4; i++) {                                          \
            CP16(sptr(&Ksm[(buf) * (64 * KST) + krow[i] * KST + kseg[i]]),     \
                 kbase + (size_t)((k0) + krow[i]) * DH + kseg[i]);             \
            CP16(sptr(&Vsm[(buf) * (64 * KST) + krow[i] * KST + kseg[i]]),     \
                 vbase + (size_t)_r[i] * CH + kseg[i]);                        \
        } CP_COMMIT; } while (0)

    // Stage Q (128x64) into stage-2 buffers: rows 0-63 -> Ksm[2], 64-127 -> Vsm[2]
    #pragma unroll
    for (int i = 0; i < 8; i++) {
        const int iidx = t + i * 128;
        const int row = iidx >> 3, u4 = (iidx & 7) * 8;
        uint4 v = *(const uint4*)(qbase + (size_t)row * DH + u4);
        __half* dst = (row < 64) ? &Ksm[2 * (64 * KST) + row * KST + u4]
                                 : &Vsm[2 * (64 * KST) + (row - 64) * KST + u4];
        *(uint4*)dst = v;
    }
    __syncthreads();

    uint32_t qf[2][4][4];
    #pragma unroll
    for (int mf = 0; mf < 2; mf++) {
        const int r = wid * 32 + mf * 16 + (lg & 1) * 8 + lr;
        const __half* qp = (r < 64) ? &Ksm[2 * (64 * KST) + r * KST + (lg >> 1) * 8]
                                    : &Vsm[2 * (64 * KST) + (r - 64) * KST + (lg >> 1) * 8];
        const uint32_t qa = sptr(qp);
        #pragma unroll
        for (int ks = 0; ks < 4; ks++)
            LDSM4(qf[mf][ks][0], qf[mf][ks][1], qf[mf][ks][2], qf[mf][ks][3],
                  qa + ks * 32);
    }

    ATTN_ISSUE(0, 0);
    if (nkt > 1) ATTN_ISSUE(1, 64);

    const uint32_t kbase_a = sptr(&Ksm[((lg >> 1) * 8 + lr) * KST + (lg & 1) * 8]);
    const uint32_t vbase_a = sptr(&Vsm[((lg & 1) * 8 + lr) * KST + (lg >> 1) * 8]);

    const uint32_t bones = (g == 0) ? 0x3C003C00u : 0u;

    float o[2][8][4] = {};
    float ol[2][4] = {};

    int cur = 0, nxt2 = 2;
    for (int kt = 0; kt < nkt; kt++) {
        const int k0 = kt * 64;
        if (kt + 1 < nkt) { CP_WAIT1; } else { CP_WAIT0; }
        __syncthreads();
        if (kt + 2 < nkt)
            ATTN_ISSUE(nxt2, k0 + 128);

        const uint32_t ko = kbase_a + cur * KSTAGE_B;
        const uint32_t vo = vbase_a + cur * KSTAGE_B;

        // S = Q K^T for both m-frags; pad-column kill only on the last tile.
        float s[2][8][4];
        if (k0 + 64 <= cnt) {
            #pragma unroll
            for (int mf = 0; mf < 2; mf++)
                #pragma unroll
                for (int nf = 0; nf < 8; nf++)
                    s[mf][nf][0] = s[mf][nf][1] = s[mf][nf][2] = s[mf][nf][3] = 0.0f;
        } else {
            #pragma unroll
            for (int nf = 0; nf < 8; nf++) {
                const int c0 = k0 + nf * 8 + tg * 2;
                const float ma = (c0     < cnt) ? 0.0f : -1000.0f;
                const float mb = (c0 + 1 < cnt) ? 0.0f : -1000.0f;
                #pragma unroll
                for (int mf = 0; mf < 2; mf++) {
                    s[mf][nf][0] = ma; s[mf][nf][1] = mb;
                    s[mf][nf][2] = ma; s[mf][nf][3] = mb;
                }
            }
        }
        #pragma unroll
        for (int ks = 0; ks < 4; ks++) {
            uint32_t bfv[4][4];
            #pragma unroll
            for (int p = 0; p < 4; p++)
                LDSM4(bfv[p][0], bfv[p][1], bfv[p][2], bfv[p][3],
                      ko + p * 16 * (KST * 2) + ks * 32);
            #pragma unroll
            for (int nf = 0; nf < 8; nf++) {
                const uint32_t b0 = bfv[nf >> 1][(nf & 1) * 2];
                const uint32_t b1 = bfv[nf >> 1][(nf & 1) * 2 + 1];
                mma_f16(s[0][nf], qf[0][ks], b0, b1, s[0][nf]);
                mma_f16(s[1][nf], qf[1][ks], b0, b1, s[1][nf]);
            }
        }

        // P = exp2(S) on packed f16x2
        uint32_t ph[2][8][2];
        #pragma unroll
        for (int mf = 0; mf < 2; mf++)
            #pragma unroll
            for (int nf = 0; nf < 8; nf++) {
                ph[mf][nf][0] = hex2(f2h2(s[mf][nf][0], s[mf][nf][1]));
                ph[mf][nf][1] = hex2(f2h2(s[mf][nf][2], s[mf][nf][3]));
            }

        // O += P V ; l += P 1 (ones-column MMA), both m-frags share V frags.
        #pragma unroll
        for (int j = 0; j < 4; j++) {
            uint32_t a0[4] = { ph[0][2 * j][0], ph[0][2 * j][1],
                               ph[0][2 * j + 1][0], ph[0][2 * j + 1][1] };
            uint32_t a1[4] = { ph[1][2 * j][0], ph[1][2 * j][1],
                               ph[1][2 * j + 1][0], ph[1][2 * j + 1][1] };
            mma_f16(ol[0], a0, bones, bones, ol[0]);
            mma_f16(ol[1], a1, bones, bones, ol[1]);
            #pragma unroll
            for (int p = 0; p < 4; p++) {
                uint32_t vf[4];
                LDSM4T(vf[0], vf[1], vf[2], vf[3],
                       vo + j * 16 * (KST * 2) + p * 32);
                mma_f16(o[0][2 * p],     a0, vf[0], vf[1], o[0][2 * p]);
                mma_f16(o[0][2 * p + 1], a0, vf[2], vf[3], o[0][2 * p + 1]);
                mma_f16(o[1][2 * p],     a1, vf[0], vf[1], o[1][2 * p]);
                mma_f16(o[1][2 * p + 1], a1, vf[2], vf[3], o[1][2 * p + 1]);
            }
        }

        cur  = (cur  == 2) ? 0 : cur + 1;
        nxt2 = (nxt2 == 2) ? 0 : nxt2 + 1;
    }

    #pragma unroll
    for (int mf = 0; mf < 2; mf++) {
        const float l0 = __shfl_sync(0xffffffffu, ol[mf][0], lid & ~3);
        const float l1 = __shfl_sync(0xffffffffu, ol[mf][2], lid & ~3);
        const float inv0 = 1.0f / l0;
        const float inv1 = 1.0f / l1;
        const int r0 = q0 + wid * 32 + mf * 16 + g;
        #pragma unroll
        for (int nf = 0; nf < 8; nf++) {
            const int d = nf * 8 + tg * 2;
            float2 v0 = make_float2(o[mf][nf][0] * inv0, o[mf][nf][1] * inv0);
            float2 v1 = make_float2(o[mf][nf][2] * inv1, o[mf][nf][3] * inv1);
            *(float2*)(out + (((size_t)b * SEQ + r0) * NH + h) * DH + d)     = v0;
            *(float2*)(out + (((size_t)b * SEQ + r0 + 8) * NH + h) * DH + d) = v1;
        }
    }
}

// ---------------------------------------------------------------------------
extern "C" void kernel_launch(void* const* d_in, const int* in_sizes, int n_in,
                              void* d_out, int out_size)
{
    const float* q_in  = (const float*)d_in[0];
    const float* k_in  = (const float*)d_in[1];
    const int*   mask  = (const int*)d_in[2];
    const float* Wq    = (const float*)d_in[3];
    const float* bq    = (const float*)d_in[4];
    const float* Wk    = (const float*)d_in[5];
    const float* bk    = (const float*)d_in[6];
    float*       out   = (float*)d_out;

    pre_kernel<<<CVT_BLOCKS + BSZ, 256>>>(mask,
                                          (const float4*)q_in, (const float4*)k_in,
                                          (const float4*)Wq, (const float4*)Wk);

    // PDL launch for proj (overlaps pre's tail)
    {
        cudaLaunchConfig_t cfg = {};
        cfg.gridDim  = dim3((BSZ * SEQ) / 128, NOUT / 128, 2);
        cfg.blockDim = dim3(256, 1, 1);
        cfg.dynamicSmemBytes = 0;
        cfg.stream = 0;
        cudaLaunchAttribute attr[1];
        attr[0].id = cudaLaunchAttributeProgrammaticStreamSerialization;
        attr[0].val.programmaticStreamSerializationAllowed = 1;
        cfg.attrs = attr;
        cfg.numAttrs = 1;
        cudaLaunchKernelEx(&cfg, proj_mma_kernel, bq, bk);
    }

    // PDL launch for attn (overlaps proj's tail)
    cudaFuncSetAttribute(attn_mma_kernel,
                         cudaFuncAttributeMaxDynamicSharedMemorySize, ATTN_SMEM);
    {
        cudaLaunchConfig_t cfg = {};
        cfg.gridDim  = dim3(SEQ / 128, BSZ * NH, 1);
        cfg.blockDim = dim3(128, 1, 1);
        cfg.dynamicSmemBytes = ATTN_SMEM;
        cfg.stream = 0;
        cudaLaunchAttribute attr[1];
        attr[0].id = cudaLaunchAttributeProgrammaticStreamSerialization;
        attr[0].val.programmaticStreamSerializationAllowed = 1;
        cfg.attrs = attr;
        cfg.numAttrs = 1;
        cudaLaunchKernelEx(&cfg, attn_mma_kernel, out);
    }
}

// round 17
// speedup vs baseline: 1.0211x; 1.0026x over previous
#include <cuda_runtime.h>
#include <cuda_fp16.h>
#include <cstdint>

#define BSZ 2
#define SEQ 2048
#define CH  1024
#define NH  16
#define DH  64
#define NOUT 1024

// fp16 copies of inputs (g_hxk doubles as the V source) + projected Q/K.
__device__ __half g_hxq[BSZ * SEQ * CH];
__device__ __half g_hxk[BSZ * SEQ * CH];
__device__ __half g_hwq[CH * NOUT];
__device__ __half g_hwk[CH * NOUT];
__device__ __half g_q[BSZ * NH * SEQ * DH];
__device__ __half g_k[BSZ * NH * SEQ * DH];   // K stored COMPACTED per batch

// Compacted unmasked-key index list per batch (padded to 128) and counts.
__device__ int g_idx[BSZ][SEQ + 128];
__device__ int g_cnt[BSZ];

#define LOG2E 1.4426950408889634f

// ---------------------------------------------------------------------------
// Helpers
// ---------------------------------------------------------------------------
__device__ __forceinline__ uint32_t f2h2(float lo, float hi) {
    __half2 h = __floats2half2_rn(lo, hi);
    return *reinterpret_cast<uint32_t*>(&h);
}
__device__ __forceinline__ uint32_t sptr(const void* p) {
    return (uint32_t)__cvta_generic_to_shared(p);
}
__device__ __forceinline__ uint32_t hex2(uint32_t x) {   // exp2 on packed f16x2
    uint32_t r;
    asm("ex2.approx.f16x2 %0, %1;" : "=r"(r) : "r"(x));
    return r;
}

__device__ __forceinline__ void mma_f16(float* d, const uint32_t* a,
                                        uint32_t b0, uint32_t b1, const float* c) {
    asm volatile(
        "mma.sync.aligned.m16n8k16.row.col.f32.f16.f16.f32 "
        "{%0,%1,%2,%3}, {%4,%5,%6,%7}, {%8,%9}, {%10,%11,%12,%13};"
        : "=f"(d[0]), "=f"(d[1]), "=f"(d[2]), "=f"(d[3])
        : "r"(a[0]), "r"(a[1]), "r"(a[2]), "r"(a[3]),
          "r"(b0), "r"(b1),
          "f"(c[0]), "f"(c[1]), "f"(c[2]), "f"(c[3]));
}

#define LDSM4(r0, r1, r2, r3, a) \
    asm volatile("ldmatrix.sync.aligned.m8n8.x4.shared.b16 {%0,%1,%2,%3}, [%4];" \
        : "=r"(r0), "=r"(r1), "=r"(r2), "=r"(r3) : "r"(a))
#define LDSM4T(r0, r1, r2, r3, a) \
    asm volatile("ldmatrix.sync.aligned.m8n8.x4.trans.shared.b16 {%0,%1,%2,%3}, [%4];" \
        : "=r"(r0), "=r"(r1), "=r"(r2), "=r"(r3) : "r"(a))

#define CP16(dst, src) \
    asm volatile("cp.async.cg.shared.global [%0], [%1], 16;" \
        :: "r"(dst), "l"(src) : "memory")
#define CP_COMMIT  asm volatile("cp.async.commit_group;" ::: "memory")
#define CP_WAIT1   asm volatile("cp.async.wait_group 1;" ::: "memory")
#define CP_WAIT0   asm volatile("cp.async.wait_group 0;" ::: "memory")

// ---------------------------------------------------------------------------
// Fused pre-pass: blocks 0..BSZ-1 compact the mask (pad idx to 128-aligned);
// the rest convert fp32->fp16. NEW: X_k rows that are MASKED are skipped
// entirely (never read downstream: K-proj and V gather go through g_idx,
// pad entries contribute p=0 exactly, and unwritten fp16 rows are finite).
// Each 256-thread group covers exactly one X_k row -> warp-uniform skip.
// ---------------------------------------------------------------------------
#define NX4 ((BSZ * SEQ * CH) / 4)   // 1048576
#define NW4 ((CH * NOUT) / 4)        // 262144
#define CVT_TOTAL (2 * NX4 + 2 * NW4)
#define CVT_BLOCKS (CVT_TOTAL / 2048)

__global__ __launch_bounds__(256) void pre_kernel(
    const int*    __restrict__ mask,
    const float4* __restrict__ xq, const float4* __restrict__ xk,
    const float4* __restrict__ wq, const float4* __restrict__ wk)
{
    cudaTriggerProgrammaticLaunchCompletion();   // let proj launch into our tail
    __shared__ __align__(16) float4 stg[2048];   // 32 KB stage
    const int t = threadIdx.x;
    if (blockIdx.x < BSZ) {
        const int b = blockIdx.x;
        __shared__ int scnt;
        if (t == 0) scnt = 0;
        __syncthreads();
        #pragma unroll
        for (int u = 0; u < SEQ / 256; u++) {
            const int j = u * 256 + t;
            const int m = mask[b * SEQ + j];
            const unsigned bal = __ballot_sync(0xffffffffu, m != 0);
            int base = 0;
            if ((t & 31) == 0) base = atomicAdd(&scnt, __popc(bal));
            base = __shfl_sync(0xffffffffu, base, 0);
            if (m) g_idx[b][base + __popc(bal & ((1u << (t & 31)) - 1u))] = j;
        }
        __syncthreads();
        const int total   = scnt;
        const int padded  = (total + 127) & ~127;
        for (int p = total + t; p < padded; p += 256) g_idx[b][p] = 0;
        if (t == 0) g_cnt[b] = total;
        return;
    }
    const int blk = blockIdx.x - BSZ;
    uint2* dp[8];
    bool live[8];
    #pragma unroll
    for (int u = 0; u < 8; u++) {
        const int i = blk * 2048 + u * 256 + t;
        const float4* src;
        uint2* dst;
        int j;
        bool lv = true;
        if (i < NX4)                { src = xq; dst = (uint2*)g_hxq; j = i; }
        else if (i < 2 * NX4) {
            src = xk; dst = (uint2*)g_hxk; j = i - NX4;
            // one row (CH floats = 256 float4) per 256-thread group: uniform skip
            lv = (mask[j >> 8] != 0);
        }
        else if (i < 2 * NX4 + NW4) { src = wq; dst = (uint2*)g_hwq; j = i - 2 * NX4; }
        else                        { src = wk; dst = (uint2*)g_hwk; j = i - 2 * NX4 - NW4; }
        if (lv) CP16(sptr(&stg[u * 256 + t]), src + j);
        dp[u] = dst + j;
        live[u] = lv;
    }
    CP_COMMIT;
    CP_WAIT0;
    __syncwarp();
    #pragma unroll
    for (int u = 0; u < 8; u++) {
        if (live[u]) {
            const float4 v = stg[u * 256 + t];
            *dp[u] = make_uint2(f2h2(v.x, v.y), f2h2(v.z, v.w));
        }
    }
}

// ---------------------------------------------------------------------------
// Projection GEMM, fp16 in/out, cp.async triple-buffered, K-step 64.
// PDL: waits on pre at entry, triggers attn's launch.
// ---------------------------------------------------------------------------
#define PXSTR 72
#define PWSTR 136
#define XSTG (128 * PXSTR * 2)
#define WSTG (64 * PWSTR * 2)
#define PROJ_NKT (CH / 64)

__global__ __launch_bounds__(256, 2) void proj_mma_kernel(
    const float* __restrict__ bq, const float* __restrict__ bk)
{
    cudaGridDependencySynchronize();             // pre outputs must be complete
    cudaTriggerProgrammaticLaunchCompletion();   // let attn launch into our tail

    __shared__ __align__(16) __half Xs[3][128][PXSTR];
    __shared__ __align__(16) __half Ws[3][64][PWSTR];

    const int t   = threadIdx.x;
    const int lid = t & 31;
    const int wid = t >> 5;
    const int warpm = wid & 3;
    const int warpn = wid >> 2;
    const int g  = lid >> 2;
    const int tg = lid & 3;
    const int lg = lid >> 3;
    const int lr = lid & 7;

    const bool is_k = (blockIdx.z != 0);
    const __half* W    = is_k ? g_hwk : g_hwq;
    const float*  bias = is_k ? bk    : bq;
    __half*       out  = is_k ? g_k   : g_q;
    const float scale  = is_k ? 1.0f : 0.125f * LOG2E;

    const int n0 = blockIdx.y * 128;

    int xrow[4], xseg[4], wrow[4], wseg[4];
    #pragma unroll
    for (int i = 0; i < 4; i++) {
        const int xi = t + i * 256;
        xrow[i] = xi >> 3;  xseg[i] = (xi & 7) * 8;
        wrow[i] = xi >> 4;  wseg[i] = (xi & 15) * 8;
    }

    int kb = 0, m0l = 0;
    int m0 = blockIdx.x * 128;
    const __half* xptr[4];
    if (!is_k) {
        #pragma unroll
        for (int i = 0; i < 4; i++)
            xptr[i] = g_hxq + (size_t)(m0 + xrow[i]) * CH;
    } else {
        kb  = blockIdx.x >> 4;
        m0l = (blockIdx.x & 15) * 128;
        const int padded = (g_cnt[kb] + 127) & ~127;
        if (m0l >= padded) return;
        #pragma unroll
        for (int i = 0; i < 4; i++)
            xptr[i] = g_hxk + ((size_t)kb * SEQ + g_idx[kb][m0l + xrow[i]]) * CH;
    }

    #define PROJ_ISSUE(buf, k0) do {                                           \
        _Pragma("unroll")                                                      \
        for (int i = 0; i < 4; i++) {                                          \
            CP16(sptr(&Xs[buf][xrow[i]][xseg[i]]), xptr[i] + (k0) + xseg[i]);  \
            CP16(sptr(&Ws[buf][wrow[i]][wseg[i]]),                             \
                 W + (size_t)((k0) + wrow[i]) * NOUT + n0 + wseg[i]);          \
        } CP_COMMIT; } while (0)

    uint32_t aaddr[2], baddr[4];
    #pragma unroll
    for (int mf = 0; mf < 2; mf++)
        aaddr[mf] = sptr(&Xs[0][warpm * 32 + mf * 16 + (lg & 1) * 8 + lr][(lg >> 1) * 8]);
    #pragma unroll
    for (int np = 0; np < 4; np++)
        baddr[np] = sptr(&Ws[0][(lg & 1) * 8 + lr][warpn * 64 + np * 16 + (lg >> 1) * 8]);

    float acc[2][8][4] = {};

    PROJ_ISSUE(0, 0);
    PROJ_ISSUE(1, 64);

    int cur = 0, nxt2 = 2;
    for (int kt = 0; kt < PROJ_NKT; kt++) {
        if (kt + 1 < PROJ_NKT) { CP_WAIT1; } else { CP_WAIT0; }
        __syncthreads();
        if (kt + 2 < PROJ_NKT)
            PROJ_ISSUE(nxt2, (kt + 2) * 64);

        const uint32_t xo = cur * XSTG;
        const uint32_t wo = cur * WSTG;
        #pragma unroll
        for (int ks = 0; ks < 4; ks++) {
            uint32_t af[2][4], bf[4][4];
            #pragma unroll
            for (int mf = 0; mf < 2; mf++)
                LDSM4(af[mf][0], af[mf][1], af[mf][2], af[mf][3],
                      aaddr[mf] + xo + ks * 32);
            #pragma unroll
            for (int np = 0; np < 4; np++)
                LDSM4T(bf[np][0], bf[np][1], bf[np][2], bf[np][3],
                       baddr[np] + wo + ks * 16 * (PWSTR * 2));
            #pragma unroll
            for (int mf = 0; mf < 2; mf++)
                #pragma unroll
                for (int nf = 0; nf < 8; nf++)
                    mma_f16(acc[mf][nf], af[mf],
                            bf[nf >> 1][(nf & 1) * 2],
                            bf[nf >> 1][(nf & 1) * 2 + 1],
                            acc[mf][nf]);
        }

        cur  = (cur  == 2) ? 0 : cur + 1;
        nxt2 = (nxt2 == 2) ? 0 : nxt2 + 1;
    }

    #pragma unroll
    for (int mf = 0; mf < 2; mf++) {
        const int rloc = warpm * 32 + mf * 16 + g;
        const int b = is_k ? kb : ((m0 + rloc) >> 11);
        const int s = is_k ? (m0l + rloc) : ((m0 + rloc) & 2047);
        #pragma unroll
        for (int nf = 0; nf < 8; nf++) {
            const int gn = n0 + warpn * 64 + nf * 8 + tg * 2;
            const int h = gn >> 6, d = gn & 63;
            const float b0v = bias[gn], b1v = bias[gn + 1];
            uint32_t v0 = f2h2((acc[mf][nf][0] + b0v) * scale,
                               (acc[mf][nf][1] + b1v) * scale);
            uint32_t v1 = f2h2((acc[mf][nf][2] + b0v) * scale,
                               (acc[mf][nf][3] + b1v) * scale);
            *(uint32_t*)(out + ((size_t)(b * NH + h) * SEQ + s) * DH + d)       = v0;
            *(uint32_t*)(out + ((size_t)(b * NH + h) * SEQ + (s + 8)) * DH + d) = v1;
        }
    }
}

// ---------------------------------------------------------------------------
// Flash attention over COMPACTED keys. 32 q-rows per warp (2 m-frags),
// 128 q-rows per CTA, triple-buffered rings. PDL: waits on proj at entry.
// ---------------------------------------------------------------------------
#define KST 72
#define KSTAGE_B (64 * KST * 2)
#define ATTN_SMEM (6 * KSTAGE_B)

__global__ __launch_bounds__(128, 2) void attn_mma_kernel(
    float* __restrict__ out)    // [B, S, H, D] fp32
{
    cudaGridDependencySynchronize();   // g_q / g_k must be complete

    extern __shared__ __align__(16) char dsm[];
    __half* Ksm = (__half*)dsm;                       // [3][64][KST]
    __half* Vsm = (__half*)(dsm + 3 * KSTAGE_B);      // [3][64][KST]

    const int t   = threadIdx.x;
    const int lid = t & 31;
    const int wid = t >> 5;
    const int g   = lid >> 2;
    const int tg  = lid & 3;
    const int lg  = lid >> 3;
    const int lr  = lid & 7;
    const int q0  = blockIdx.x * 128;
    const int bh  = blockIdx.y;
    const int b   = bh >> 4;
    const int h   = bh & 15;

    const __half* qbase = g_q + ((size_t)bh * SEQ + q0) * DH;
    const __half* kbase = g_k + (size_t)bh * SEQ * DH;     // compacted rows
    const __half* vbase = g_hxk + (size_t)b * SEQ * CH + h * DH;
    const int*    idx   = g_idx[b];

    const int cnt = g_cnt[b];
    const int nkt = (cnt + 63) >> 6;

    const int krow[4] = { (t + 0) >> 3, (t + 128) >> 3, (t + 256) >> 3, (t + 384) >> 3 };
    const int kseg[4] = { ((t + 0) & 7) * 8, ((t + 128) & 7) * 8,
                          ((t + 256) & 7) * 8, ((t + 384) & 7) * 8 };

    #define ATTN_ISSUE(buf, k0) do {                                           \
        int _r[4];                                                             \
        _Pragma("unroll")                                                      \
        for (int i = 0; i < 4; i++) _r[i] = idx[(k0) + krow[i]];               \
        _Pragma("unroll")                                                      \
        for (int i = 0; i < 4; i++) {                                          \
            CP16(sptr(&Ksm[(buf) * (64 * KST) + krow[i] * KST + kseg[i]]),     \
                 kbase + (size_t)((k0) + krow[i]) * DH + kseg[i]);             \
            CP16(sptr(&Vsm[(buf) * (64 * KST) + krow[i] * KST + kseg[i]]),     \
                 vbase + (size_t)_r[i] * CH + kseg[i]);                        \
        } CP_COMMIT; } while (0)

    // Stage Q (128x64) into stage-2 buffers: rows 0-63 -> Ksm[2], 64-127 -> Vsm[2]
    #pragma unroll
    for (int i = 0; i < 8; i++) {
        const int iidx = t + i * 128;
        const int row = iidx >> 3, u4 = (iidx & 7) * 8;
        uint4 v = *(const uint4*)(qbase + (size_t)row * DH + u4);
        __half* dst = (row < 64) ? &Ksm[2 * (64 * KST) + row * KST + u4]
                                 : &Vsm[2 * (64 * KST) + (row - 64) * KST + u4];
        *(uint4*)dst = v;
    }
    __syncthreads();

    uint32_t qf[2][4][4];
    #pragma unroll
    for (int mf = 0; mf < 2; mf++) {
        const int r = wid * 32 + mf * 16 + (lg & 1) * 8 + lr;
        const __half* qp = (r < 64) ? &Ksm[2 * (64 * KST) + r * KST + (lg >> 1) * 8]
                                    : &Vsm[2 * (64 * KST) + (r - 64) * KST + (lg >> 1) * 8];
        const uint32_t qa = sptr(qp);
        #pragma unroll
        for (int ks = 0; ks < 4; ks++)
            LDSM4(qf[mf][ks][0], qf[mf][ks][1], qf[mf][ks][2], qf[mf][ks][3],
                  qa + ks * 32);
    }

    ATTN_ISSUE(0, 0);
    if (nkt > 1) ATTN_ISSUE(1, 64);

    const uint32_t kbase_a = sptr(&Ksm[((lg >> 1) * 8 + lr) * KST + (lg & 1) * 8]);
    const uint32_t vbase_a = sptr(&Vsm[((lg & 1) * 8 + lr) * KST + (lg >> 1) * 8]);

    const uint32_t bones = (g == 0) ? 0x3C003C00u : 0u;

    float o[2][8][4] = {};
    float ol[2][4] = {};

    int cur = 0, nxt2 = 2;
    for (int kt = 0; kt < nkt; kt++) {
        const int k0 = kt * 64;
        if (kt + 1 < nkt) { CP_WAIT1; } else { CP_WAIT0; }
        __syncthreads();
        if (kt + 2 < nkt)
            ATTN_ISSUE(nxt2, k0 + 128);

        const uint32_t ko = kbase_a + cur * KSTAGE_B;
        const uint32_t vo = vbase_a + cur * KSTAGE_B;

        // S = Q K^T for both m-frags; pad-column kill only on the last tile.
        float s[2][8][4];
        if (k0 + 64 <= cnt) {
            #pragma unroll
            for (int mf = 0; mf < 2; mf++)
                #pragma unroll
                for (int nf = 0; nf < 8; nf++)
                    s[mf][nf][0] = s[mf][nf][1] = s[mf][nf][2] = s[mf][nf][3] = 0.0f;
        } else {
            #pragma unroll
            for (int nf = 0; nf < 8; nf++) {
                const int c0 = k0 + nf * 8 + tg * 2;
                const float ma = (c0     < cnt) ? 0.0f : -1000.0f;
                const float mb = (c0 + 1 < cnt) ? 0.0f : -1000.0f;
                #pragma unroll
                for (int mf = 0; mf < 2; mf++) {
                    s[mf][nf][0] = ma; s[mf][nf][1] = mb;
                    s[mf][nf][2] = ma; s[mf][nf][3] = mb;
                }
            }
        }
        #pragma unroll
        for (int ks = 0; ks < 4; ks++) {
            uint32_t bfv[4][4];
            #pragma unroll
            for (int p = 0; p < 4; p++)
                LDSM4(bfv[p][0], bfv[p][1], bfv[p][2], bfv[p][3],
                      ko + p * 16 * (KST * 2) + ks * 32);
            #pragma unroll
            for (int nf = 0; nf < 8; nf++) {
                const uint32_t b0 = bfv[nf >> 1][(nf & 1) * 2];
                const uint32_t b1 = bfv[nf >> 1][(nf & 1) * 2 + 1];
                mma_f16(s[0][nf], qf[0][ks], b0, b1, s[0][nf]);
                mma_f16(s[1][nf], qf[1][ks], b0, b1, s[1][nf]);
            }
        }

        // P = exp2(S) on packed f16x2
        uint32_t ph[2][8][2];
        #pragma unroll
        for (int mf = 0; mf < 2; mf++)
            #pragma unroll
            for (int nf = 0; nf < 8; nf++) {
                ph[mf][nf][0] = hex2(f2h2(s[mf][nf][0], s[mf][nf][1]));
                ph[mf][nf][1] = hex2(f2h2(s[mf][nf][2], s[mf][nf][3]));
            }

        // O += P V ; l += P 1 (ones-column MMA), both m-frags share V frags.
        #pragma unroll
        for (int j = 0; j < 4; j++) {
            uint32_t a0[4] = { ph[0][2 * j][0], ph[0][2 * j][1],
                               ph[0][2 * j + 1][0], ph[0][2 * j + 1][1] };
            uint32_t a1[4] = { ph[1][2 * j][0], ph[1][2 * j][1],
                               ph[1][2 * j + 1][0], ph[1][2 * j + 1][1] };
            mma_f16(ol[0], a0, bones, bones, ol[0]);
            mma_f16(ol[1], a1, bones, bones, ol[1]);
            #pragma unroll
            for (int p = 0; p < 4; p++) {
                uint32_t vf[4];
                LDSM4T(vf[0], vf[1], vf[2], vf[3],
                       vo + j * 16 * (KST * 2) + p * 32);
                mma_f16(o[0][2 * p],     a0, vf[0], vf[1], o[0][2 * p]);
                mma_f16(o[0][2 * p + 1], a0, vf[2], vf[3], o[0][2 * p + 1]);
                mma_f16(o[1][2 * p],     a1, vf[0], vf[1], o[1][2 * p]);
                mma_f16(o[1][2 * p + 1], a1, vf[2], vf[3], o[1][2 * p + 1]);
            }
        }

        cur  = (cur  == 2) ? 0 : cur + 1;
        nxt2 = (nxt2 == 2) ? 0 : nxt2 + 1;
    }

    #pragma unroll
    for (int mf = 0; mf < 2; mf++) {
        const float l0 = __shfl_sync(0xffffffffu, ol[mf][0], lid & ~3);
        const float l1 = __shfl_sync(0xffffffffu, ol[mf][2], lid & ~3);
        const float inv0 = 1.0f / l0;
        const float inv1 = 1.0f / l1;
        const int r0 = q0 + wid * 32 + mf * 16 + g;
        #pragma unroll
        for (int nf = 0; nf < 8; nf++) {
            const int d = nf * 8 + tg * 2;
            float2 v0 = make_float2(o[mf][nf][0] * inv0, o[mf][nf][1] * inv0);
            float2 v1 = make_float2(o[mf][nf][2] * inv1, o[mf][nf][3] * inv1);
            *(float2*)(out + (((size_t)b * SEQ + r0) * NH + h) * DH + d)     = v0;
            *(float2*)(out + (((size_t)b * SEQ + r0 + 8) * NH + h) * DH + d) = v1;
        }
    }
}

// ---------------------------------------------------------------------------
extern "C" void kernel_launch(void* const* d_in, const int* in_sizes, int n_in,
                              void* d_out, int out_size)
{
    const float* q_in  = (const float*)d_in[0];
    const float* k_in  = (const float*)d_in[1];
    const int*   mask  = (const int*)d_in[2];
    const float* Wq    = (const float*)d_in[3];
    const float* bq    = (const float*)d_in[4];
    const float* Wk    = (const float*)d_in[5];
    const float* bk    = (const float*)d_in[6];
    float*       out   = (float*)d_out;

    pre_kernel<<<CVT_BLOCKS + BSZ, 256>>>(mask,
                                          (const float4*)q_in, (const float4*)k_in,
                                          (const float4*)Wq, (const float4*)Wk);

    // PDL launch for proj (overlaps pre's tail)
    {
        cudaLaunchConfig_t cfg = {};
        cfg.gridDim  = dim3((BSZ * SEQ) / 128, NOUT / 128, 2);
        cfg.blockDim = dim3(256, 1, 1);
        cfg.dynamicSmemBytes = 0;
        cfg.stream = 0;
        cudaLaunchAttribute attr[1];
        attr[0].id = cudaLaunchAttributeProgrammaticStreamSerialization;
        attr[0].val.programmaticStreamSerializationAllowed = 1;
        cfg.attrs = attr;
        cfg.numAttrs = 1;
        cudaLaunchKernelEx(&cfg, proj_mma_kernel, bq, bk);
    }

    // PDL launch for attn (overlaps proj's tail)
    cudaFuncSetAttribute(attn_mma_kernel,
                         cudaFuncAttributeMaxDynamicSharedMemorySize, ATTN_SMEM);
    {
        cudaLaunchConfig_t cfg = {};
        cfg.gridDim  = dim3(SEQ / 128, BSZ * NH, 1);
        cfg.blockDim = dim3(128, 1, 1);
        cfg.dynamicSmemBytes = ATTN_SMEM;
        cfg.stream = 0;
        cudaLaunchAttribute attr[1];
        attr[0].id = cudaLaunchAttributeProgrammaticStreamSerialization;
        attr[0].val.programmaticStreamSerializationAllowed = 1;
        cfg.attrs = attr;
        cfg.numAttrs = 1;
        cudaLaunchKernelEx(&cfg, attn_mma_kernel, out);
    }
}